// round 5
// baseline (speedup 1.0000x reference)
#include <cuda_runtime.h>
#include <math.h>

// Problem constants (fixed by the reference)
#define BB 4
#define SS 1024
#define DD 1024
#define HH 16
#define HD 64

// Scratch (allocation-free rule: __device__ globals)
__device__ float g_Q[BB*HH*SS*HD];   // [B,H,S,Hd]
__device__ float g_K[BB*HH*SS*HD];
__device__ float g_V[BB*HH*SS*HD];
__device__ float g_ctx[BB*SS*DD];    // [B,S,D]

// ---------------------------------------------------------------------------
// SGEMM: Y = X @ W^T,  M=4096, N=1024, K=1024 (fp32, 128x128x16, 8x8/thread)
// ---------------------------------------------------------------------------
#define BM 128
#define BN 128
#define BKg 16

template<int MODE>  // 0 = scatter to [B,H,S,Hd], 1 = plain row-major [M,N]
__device__ __forceinline__ void gemm_body(const float* __restrict__ X,
                                          const float* __restrict__ W,
                                          float* __restrict__ Y)
{
    __shared__ float As[BKg][BM];
    __shared__ float Bs[BKg][BN];
    const int K = 1024, N = 1024;

    int tid = threadIdx.x;
    int tx = tid & 15, ty = tid >> 4;
    int m0 = blockIdx.y * BM, n0 = blockIdx.x * BN;

    float acc[8][8];
    #pragma unroll
    for (int i = 0; i < 8; i++)
        #pragma unroll
        for (int j = 0; j < 8; j++) acc[i][j] = 0.f;

    for (int k0 = 0; k0 < K; k0 += BKg) {
        // A tile: 128 rows x 16 k, stored transposed As[k][m]
        #pragma unroll
        for (int l = 0; l < 2; l++) {
            int idx = tid + l * 256;
            int ar = idx >> 2;
            int ac = (idx & 3) * 4;
            float4 f = *(const float4*)&X[(size_t)(m0 + ar) * K + k0 + ac];
            As[ac+0][ar] = f.x; As[ac+1][ar] = f.y;
            As[ac+2][ar] = f.z; As[ac+3][ar] = f.w;
        }
        // B tile: W is [N,K] row-major; Bs[k][n] = W[n][k]
        #pragma unroll
        for (int l = 0; l < 2; l++) {
            int idx = tid + l * 256;
            int br = idx >> 2;
            int bc = (idx & 3) * 4;
            float4 f = *(const float4*)&W[(size_t)(n0 + br) * K + k0 + bc];
            Bs[bc+0][br] = f.x; Bs[bc+1][br] = f.y;
            Bs[bc+2][br] = f.z; Bs[bc+3][br] = f.w;
        }
        __syncthreads();

        #pragma unroll
        for (int kk = 0; kk < BKg; kk++) {
            float4 a0 = *(const float4*)&As[kk][ty*8];
            float4 a1 = *(const float4*)&As[kk][ty*8+4];
            float4 b0 = *(const float4*)&Bs[kk][tx*8];
            float4 b1 = *(const float4*)&Bs[kk][tx*8+4];
            float a[8] = {a0.x,a0.y,a0.z,a0.w,a1.x,a1.y,a1.z,a1.w};
            float b[8] = {b0.x,b0.y,b0.z,b0.w,b1.x,b1.y,b1.z,b1.w};
            #pragma unroll
            for (int i = 0; i < 8; i++)
                #pragma unroll
                for (int j = 0; j < 8; j++)
                    acc[i][j] = fmaf(a[i], b[j], acc[i][j]);
        }
        __syncthreads();
    }

    #pragma unroll
    for (int i = 0; i < 8; i++) {
        int m = m0 + ty*8 + i;
        #pragma unroll
        for (int j = 0; j < 8; j++) {
            int n = n0 + tx*8 + j;
            if (MODE == 0) {
                int b = m >> 10, s = m & 1023, h = n >> 6, d = n & 63;
                Y[(((size_t)(b*HH + h)) * SS + s) * HD + d] = acc[i][j];
            } else {
                Y[(size_t)m * N + n] = acc[i][j];
            }
        }
    }
}

__global__ __launch_bounds__(256) void proj_kernel(const float* __restrict__ q,
                                                   const float* __restrict__ k,
                                                   const float* __restrict__ v,
                                                   const float* __restrict__ Wq)
{
    const float* X = (blockIdx.z == 0) ? q : (blockIdx.z == 1) ? k : v;
    float* Y = (blockIdx.z == 0) ? g_Q : (blockIdx.z == 1) ? g_K : g_V;
    gemm_body<0>(X, Wq, Y);
}

__global__ __launch_bounds__(256) void out_kernel(const float* __restrict__ Wout,
                                                  float* __restrict__ out)
{
    gemm_body<1>(g_ctx, Wout, out);
}

// ---------------------------------------------------------------------------
// Flash attention with ALiBi bias.  Per block: one (b,h), 64 query rows.
// Tiles of 64 keys; online softmax; P routed through smem (reuses K buffer).
// ---------------------------------------------------------------------------
#define LDA 68   // padded leading dim (floats); 68*4 bytes keeps 16B alignment

__global__ __launch_bounds__(256) void attn_kernel(const int* __restrict__ mask)
{
    extern __shared__ float sm[];
    float* Qt  = sm;               // [64 dims][LDA rows]  (Q transposed)
    float* KPt = sm + 64*LDA;      // K transposed, then P transposed [key][row]
    float* Vs  = sm + 2*64*LDA;    // [key][LDA dims]
    __shared__ float maskneg[64];  // 0 or nonzero flag (-1e9) per key

    int tid = threadIdx.x;
    int tx = tid & 15, ty = tid >> 4;
    int bh = blockIdx.y;
    int b = bh >> 4, h = bh & 15;
    int q0 = blockIdx.x * 64;
    const float slope = exp2f(-0.5f * (float)(h + 1));

    const float* Qg = g_Q + ((size_t)bh * SS + q0) * HD;
    const float* Kg = g_K + (size_t)bh * SS * HD;
    const float* Vg = g_V + (size_t)bh * SS * HD;

    // Load Q tile transposed: Qt[dim][row]
    #pragma unroll
    for (int l = 0; l < 4; l++) {
        int idx = tid + l * 256;
        int r = idx >> 4;
        int c = (idx & 15) * 4;
        float4 f = *(const float4*)&Qg[r*HD + c];
        Qt[(c+0)*LDA + r] = f.x; Qt[(c+1)*LDA + r] = f.y;
        Qt[(c+2)*LDA + r] = f.z; Qt[(c+3)*LDA + r] = f.w;
    }

    float m_run[4], l_run[4], o[4][4];
    #pragma unroll
    for (int i = 0; i < 4; i++) {
        m_run[i] = -1e30f; l_run[i] = 0.f;
        #pragma unroll
        for (int j = 0; j < 4; j++) o[i][j] = 0.f;
    }

    #pragma unroll 1
    for (int kt = 0; kt < 16; kt++) {
        int kbase = kt * 64;
        // Load K (transposed) and V (direct) tiles
        #pragma unroll
        for (int l = 0; l < 4; l++) {
            int idx = tid + l * 256;
            int r = idx >> 4;
            int c = (idx & 15) * 4;
            float4 f = *(const float4*)&Kg[(size_t)(kbase + r)*HD + c];
            KPt[(c+0)*LDA + r] = f.x; KPt[(c+1)*LDA + r] = f.y;
            KPt[(c+2)*LDA + r] = f.z; KPt[(c+3)*LDA + r] = f.w;
            float4 g = *(const float4*)&Vg[(size_t)(kbase + r)*HD + c];
            *(float4*)&Vs[r*LDA + c] = g;
        }
        if (tid < 64)
            maskneg[tid] = (mask[b*SS + kbase + tid] == 0) ? -1e9f : 0.f;
        __syncthreads();

        // S = Q K^T  (4x4 per thread)
        float s[4][4];
        #pragma unroll
        for (int i = 0; i < 4; i++)
            #pragma unroll
            for (int j = 0; j < 4; j++) s[i][j] = 0.f;

        #pragma unroll 16
        for (int kk = 0; kk < 64; kk++) {
            float4 a  = *(const float4*)&Qt[kk*LDA + ty*4];
            float4 bb = *(const float4*)&KPt[kk*LDA + tx*4];
            float av[4] = {a.x, a.y, a.z, a.w};
            float bv[4] = {bb.x, bb.y, bb.z, bb.w};
            #pragma unroll
            for (int i = 0; i < 4; i++)
                #pragma unroll
                for (int j = 0; j < 4; j++)
                    s[i][j] = fmaf(av[i], bv[j], s[i][j]);
        }

        // ALiBi bias + mask
        #pragma unroll
        for (int i = 0; i < 4; i++) {
            int qi = q0 + ty*4 + i;
            #pragma unroll
            for (int j = 0; j < 4; j++) {
                int kj = kbase + tx*4 + j;
                if (kj <= qi) s[i][j] += slope * (float)(kj - qi);
                if (maskneg[tx*4 + j] != 0.f) s[i][j] = -1e9f;
            }
        }

        // Online softmax update (rows spread across 16 lanes: tx groups)
        #pragma unroll
        for (int i = 0; i < 4; i++) {
            float mt = fmaxf(fmaxf(s[i][0], s[i][1]), fmaxf(s[i][2], s[i][3]));
            #pragma unroll
            for (int off = 1; off < 16; off <<= 1)
                mt = fmaxf(mt, __shfl_xor_sync(0xffffffffu, mt, off));
            float nm = fmaxf(m_run[i], mt);
            float corr = __expf(m_run[i] - nm);
            float rs = 0.f;
            #pragma unroll
            for (int j = 0; j < 4; j++) {
                s[i][j] = __expf(s[i][j] - nm);
                rs += s[i][j];
            }
            #pragma unroll
            for (int off = 1; off < 16; off <<= 1)
                rs += __shfl_xor_sync(0xffffffffu, rs, off);
            l_run[i] = l_run[i] * corr + rs;
            m_run[i] = nm;
            #pragma unroll
            for (int j = 0; j < 4; j++) o[i][j] *= corr;
        }

        __syncthreads();  // done reading KPt as K
        // Write P transposed: KPt[key][row]
        #pragma unroll
        for (int i = 0; i < 4; i++)
            #pragma unroll
            for (int j = 0; j < 4; j++)
                KPt[(tx*4 + j)*LDA + ty*4 + i] = s[i][j];
        __syncthreads();

        // O += P V
        #pragma unroll 16
        for (int kk = 0; kk < 64; kk++) {
            float4 p  = *(const float4*)&KPt[kk*LDA + ty*4];
            float4 vv = *(const float4*)&Vs[kk*LDA + tx*4];
            float pv[4] = {p.x, p.y, p.z, p.w};
            float vvv[4] = {vv.x, vv.y, vv.z, vv.w};
            #pragma unroll
            for (int i = 0; i < 4; i++)
                #pragma unroll
                for (int j = 0; j < 4; j++)
                    o[i][j] = fmaf(pv[i], vvv[j], o[i][j]);
        }
        __syncthreads();  // before next tile overwrites KPt/Vs
    }

    // Normalize and write ctx in [B,S,D] layout
    #pragma unroll
    for (int i = 0; i < 4; i++) {
        float inv = 1.f / l_run[i];
        int srow = q0 + ty*4 + i;
        #pragma unroll
        for (int j = 0; j < 4; j++)
            g_ctx[((size_t)b * SS + srow) * DD + h*HD + tx*4 + j] = o[i][j] * inv;
    }
}

// ---------------------------------------------------------------------------
extern "C" void kernel_launch(void* const* d_in, const int* in_sizes, int n_in,
                              void* d_out, int out_size)
{
    const float* q    = (const float*)d_in[0];
    const float* k    = (const float*)d_in[1];
    const float* v    = (const float*)d_in[2];
    const int*   mask = (const int*)d_in[3];
    const float* Wq   = (const float*)d_in[4];
    const float* Wout = (const float*)d_in[5];
    float* out = (float*)d_out;

    const int attn_smem = 3 * 64 * LDA * (int)sizeof(float);  // 52224 bytes
    cudaFuncSetAttribute(attn_kernel, cudaFuncAttributeMaxDynamicSharedMemorySize,
                         attn_smem);

    // Q/K/V projections (all use Wq, faithful to the reference "bug")
    proj_kernel<<<dim3(8, 32, 3), 256>>>(q, k, v, Wq);
    // Flash attention with ALiBi
    attn_kernel<<<dim3(16, 64), 256, attn_smem>>>(mask);
    // Output projection
    out_kernel<<<dim3(8, 32), 256>>>(Wout, out);
}